// round 1
// baseline (speedup 1.0000x reference)
#include <cuda_runtime.h>
#include <cstddef>

// ---------------------------------------------------------------------------
// GeoDynamicLayer: out = x @ W^T where W = RK4-solve of dU/dt = U A + G.
//
// Key factorization: A = La D Ra^T - Ra D La^T (D = diag(abar)),
// G = [0; Lb Db Rb^T].  Every RK4 stage has row space spanned by
// V2 = [La | Ra | Rb] (512x24).  Writing U = U0 + P V2^T (P: 1024x24):
//   f(U0 + P V2^T) = (F0 + P S) V2^T
//   F0[:,0:8]  = -(U0 Ra) D,  F0[:,8:16] = (U0 La) D,  F0[:,16:24] = E Db
//   S[k][c<8]  = -(V2^T Ra)[k][c] * abar_c
//   S[k][8+r]  =  (V2^T La)[k][r] * abar_r ,  S[:,16:24] = 0
// RK4 runs exactly (same linear combinations as reference) in P-space.
// Then W = U0 + P V2^T, and the big GEMM out = x @ W^T.
// ---------------------------------------------------------------------------

__device__ float g_partial[256 * 512];
__device__ float g_ab[16];          // [0:8]=abar, [8:16]=bbar
__device__ float g_S[24 * 16];
__device__ float g_F0[1024 * 24];
__device__ float g_P[1024 * 24];
__device__ float g_W[1024 * 512];

// ---------------- Stage 1: column sums of x (32768 x 512) -------------------
__global__ void reduce_partial_k(const float* __restrict__ x) {
    int t = threadIdx.x;                 // 0..511 = column
    int rowStart = blockIdx.x * 128;     // 256 blocks * 128 rows = 32768
    const float* p = x + (size_t)rowStart * 512 + t;
    float s = 0.f;
    #pragma unroll 8
    for (int r = 0; r < 128; ++r) s += p[(size_t)r * 512];
    g_partial[blockIdx.x * 512 + t] = s;
}

// ---------------- Stage 2: xbar, abar = xbar@Wa, bbar = xbar@Wb -------------
__global__ void finalize_ab_k(const float* __restrict__ Wa,
                              const float* __restrict__ Wb) {
    __shared__ float sx[512];
    int t = threadIdx.x;                 // 512 threads = 16 warps
    float s = 0.f;
    #pragma unroll 8
    for (int p = 0; p < 256; ++p) s += g_partial[p * 512 + t];
    s *= (1.0f / 32768.0f);              // mean over batch(8) * seq(4096)
    sx[t] = s;
    __syncthreads();
    int w = t >> 5, lane = t & 31;       // warp w computes g_ab[w]
    const float* Wm = (w < 8) ? Wa : Wb;
    int r = w & 7;
    float acc = 0.f;
    #pragma unroll
    for (int q = 0; q < 16; ++q) {
        int i = lane + q * 32;
        acc += sx[i] * Wm[i * 8 + r];
    }
    #pragma unroll
    for (int off = 16; off; off >>= 1)
        acc += __shfl_xor_sync(0xffffffffu, acc, off);
    if (lane == 0) g_ab[w] = acc;
}

// ---------------- Stage 3: S (24x16) ----------------------------------------
__global__ void compute_S_k(const float* __restrict__ La,
                            const float* __restrict__ Ra,
                            const float* __restrict__ Rb) {
    int gw = (blockIdx.x * blockDim.x + threadIdx.x) >> 5;  // 384 warps
    int lane = threadIdx.x & 31;
    if (gw >= 384) return;
    int k = gw >> 4, c = gw & 15;
    const float* Vk = (k < 8) ? La : ((k < 16) ? Ra : Rb);
    int kk = k & 7;
    const float* M = (c < 8) ? Ra : La;
    int r = c & 7;
    float acc = 0.f;
    #pragma unroll
    for (int q = 0; q < 16; ++q) {
        int i = lane + q * 32;
        acc += Vk[i * 8 + kk] * M[i * 8 + r];
    }
    #pragma unroll
    for (int off = 16; off; off >>= 1)
        acc += __shfl_xor_sync(0xffffffffu, acc, off);
    if (lane == 0) {
        float d = g_ab[r];
        g_S[k * 16 + c] = (c < 8) ? (-acc * d) : (acc * d);
    }
}

// ---------------- Stage 4: F0 (1024x24) -------------------------------------
__global__ void compute_F0_k(const float* __restrict__ U0,
                             const float* __restrict__ La,
                             const float* __restrict__ Ra,
                             const float* __restrict__ Lb) {
    int w = (blockIdx.x * blockDim.x + threadIdx.x) >> 5;   // row 0..1023
    int lane = threadIdx.x & 31;
    const float* u = U0 + (size_t)w * 512;
    float accA[8] = {0, 0, 0, 0, 0, 0, 0, 0};   // u . La[:,r]
    float accR[8] = {0, 0, 0, 0, 0, 0, 0, 0};   // u . Ra[:,r]
    #pragma unroll
    for (int q = 0; q < 16; ++q) {
        int i = lane + q * 32;
        float uv = u[i];
        float4 la0 = *(const float4*)(La + i * 8);
        float4 la1 = *(const float4*)(La + i * 8 + 4);
        float4 ra0 = *(const float4*)(Ra + i * 8);
        float4 ra1 = *(const float4*)(Ra + i * 8 + 4);
        accA[0] += uv * la0.x; accA[1] += uv * la0.y;
        accA[2] += uv * la0.z; accA[3] += uv * la0.w;
        accA[4] += uv * la1.x; accA[5] += uv * la1.y;
        accA[6] += uv * la1.z; accA[7] += uv * la1.w;
        accR[0] += uv * ra0.x; accR[1] += uv * ra0.y;
        accR[2] += uv * ra0.z; accR[3] += uv * ra0.w;
        accR[4] += uv * ra1.x; accR[5] += uv * ra1.y;
        accR[6] += uv * ra1.z; accR[7] += uv * ra1.w;
    }
    #pragma unroll
    for (int off = 16; off; off >>= 1) {
        #pragma unroll
        for (int r = 0; r < 8; ++r) {
            accA[r] += __shfl_xor_sync(0xffffffffu, accA[r], off);
            accR[r] += __shfl_xor_sync(0xffffffffu, accR[r], off);
        }
    }
    if (lane == 0) {
        #pragma unroll
        for (int r = 0; r < 8; ++r) {
            float da = g_ab[r];
            g_F0[w * 24 + r]     = -da * accR[r];
            g_F0[w * 24 + 8 + r] =  da * accA[r];
            float gb = 0.f;
            if (w >= 512) gb = g_ab[8 + r] * Lb[(w - 512) * 8 + r];
            g_F0[w * 24 + 16 + r] = gb;
        }
    }
}

// ---------------- Stage 5: RK4 in 24-dim coefficient space ------------------
// One warp per row of P.  Lane c holds S column c (zero for c>=16) and f0_c.
// Full p/v/acc vectors kept replicated per-lane; stage results broadcast via
// shfl.  Exactly mirrors reference RK4 linear combinations.
__global__ void rk4_k() {
    int row = (blockIdx.x * blockDim.x + threadIdx.x) >> 5;  // 1024 warps
    int lane = threadIdx.x & 31;
    float scol[24];
    #pragma unroll
    for (int k = 0; k < 24; ++k)
        scol[k] = (lane < 16) ? g_S[k * 16 + lane] : 0.f;
    float f0 = (lane < 24) ? g_F0[row * 24 + lane] : 0.f;
    float p[24];
    #pragma unroll
    for (int k = 0; k < 24; ++k) p[k] = 0.f;
    const float dt = 1.0f / 8.0f;
    for (int step = 0; step < 8; ++step) {
        float v[24], acc[24];
        #pragma unroll
        for (int k = 0; k < 24; ++k) v[k] = p[k];
        // ---- stage 1 ----
        float kc = f0;
        #pragma unroll
        for (int k = 0; k < 24; ++k) kc += v[k] * scol[k];
        #pragma unroll
        for (int k = 0; k < 24; ++k) {
            float kf = __shfl_sync(0xffffffffu, kc, k);
            acc[k] = kf;
            v[k] = p[k] + 0.5f * dt * kf;
        }
        // ---- stage 2 ----
        kc = f0;
        #pragma unroll
        for (int k = 0; k < 24; ++k) kc += v[k] * scol[k];
        #pragma unroll
        for (int k = 0; k < 24; ++k) {
            float kf = __shfl_sync(0xffffffffu, kc, k);
            acc[k] += 2.0f * kf;
            v[k] = p[k] + 0.5f * dt * kf;
        }
        // ---- stage 3 ----
        kc = f0;
        #pragma unroll
        for (int k = 0; k < 24; ++k) kc += v[k] * scol[k];
        #pragma unroll
        for (int k = 0; k < 24; ++k) {
            float kf = __shfl_sync(0xffffffffu, kc, k);
            acc[k] += 2.0f * kf;
            v[k] = p[k] + dt * kf;
        }
        // ---- stage 4 ----
        kc = f0;
        #pragma unroll
        for (int k = 0; k < 24; ++k) kc += v[k] * scol[k];
        #pragma unroll
        for (int k = 0; k < 24; ++k) {
            float kf = __shfl_sync(0xffffffffu, kc, k);
            acc[k] += kf;
        }
        #pragma unroll
        for (int k = 0; k < 24; ++k) p[k] += (dt / 6.0f) * acc[k];
    }
    if (lane < 24) g_P[row * 24 + lane] = p[lane];
}

// ---------------- Stage 6: expand W = U0 + P V2^T ---------------------------
__global__ void expand_W_k(const float* __restrict__ U0,
                           const float* __restrict__ La,
                           const float* __restrict__ Ra,
                           const float* __restrict__ Rb) {
    __shared__ float sP[8 * 24];
    int t = threadIdx.x;                 // 256 threads
    int o0 = blockIdx.x * 8;             // 128 blocks x 8 rows
    if (t < 192) sP[t] = g_P[o0 * 24 + t];
    __syncthreads();
    #pragma unroll
    for (int half = 0; half < 2; ++half) {
        int i = t + half * 256;          // column 0..511
        float v2[24];
        float4 q;
        q = *(const float4*)(La + i * 8);
        v2[0] = q.x; v2[1] = q.y; v2[2] = q.z; v2[3] = q.w;
        q = *(const float4*)(La + i * 8 + 4);
        v2[4] = q.x; v2[5] = q.y; v2[6] = q.z; v2[7] = q.w;
        q = *(const float4*)(Ra + i * 8);
        v2[8] = q.x; v2[9] = q.y; v2[10] = q.z; v2[11] = q.w;
        q = *(const float4*)(Ra + i * 8 + 4);
        v2[12] = q.x; v2[13] = q.y; v2[14] = q.z; v2[15] = q.w;
        q = *(const float4*)(Rb + i * 8);
        v2[16] = q.x; v2[17] = q.y; v2[18] = q.z; v2[19] = q.w;
        q = *(const float4*)(Rb + i * 8 + 4);
        v2[20] = q.x; v2[21] = q.y; v2[22] = q.z; v2[23] = q.w;
        #pragma unroll
        for (int r = 0; r < 8; ++r) {
            float accv = U0[(size_t)(o0 + r) * 512 + i];
            #pragma unroll
            for (int k = 0; k < 24; ++k) accv += sP[r * 24 + k] * v2[k];
            g_W[(size_t)(o0 + r) * 512 + i] = accv;
        }
    }
}

// ---------------- Stage 7: out = x @ W^T  (32768 x 1024, K=512) -------------
// 128x128 block tile, BK=16, 256 threads, 8x8 per thread, double-buffered smem.
__global__ __launch_bounds__(256, 2) void gemm_k(const float* __restrict__ X,
                                                 float* __restrict__ out) {
    __shared__ __align__(16) float As[2][16][132];
    __shared__ __align__(16) float Bs[2][16][132];
    int tid = threadIdx.x;
    int bm = blockIdx.y * 128;
    int bn = blockIdx.x * 128;
    int lrow = tid >> 2;            // 0..63
    int lkq = (tid & 3) * 4;        // 0,4,8,12
    int tx = tid & 15, ty = tid >> 4;
    int m0 = ty * 8, n0 = tx * 8;
    const float* Wp = g_W;

    float acc[8][8];
    #pragma unroll
    for (int i2 = 0; i2 < 8; ++i2)
        #pragma unroll
        for (int j = 0; j < 8; ++j) acc[i2][j] = 0.f;

    // preload tile 0
    #pragma unroll
    for (int s = 0; s < 2; ++s) {
        int row = lrow + s * 64;
        float4 va = *(const float4*)(X + (size_t)(bm + row) * 512 + lkq);
        As[0][lkq + 0][row] = va.x; As[0][lkq + 1][row] = va.y;
        As[0][lkq + 2][row] = va.z; As[0][lkq + 3][row] = va.w;
        float4 vb = *(const float4*)(Wp + (size_t)(bn + row) * 512 + lkq);
        Bs[0][lkq + 0][row] = vb.x; Bs[0][lkq + 1][row] = vb.y;
        Bs[0][lkq + 2][row] = vb.z; Bs[0][lkq + 3][row] = vb.w;
    }
    __syncthreads();

    for (int kt = 0; kt < 32; ++kt) {
        int buf = kt & 1;
        if (kt + 1 < 32) {
            int k0 = (kt + 1) * 16;
            int nb = buf ^ 1;
            #pragma unroll
            for (int s = 0; s < 2; ++s) {
                int row = lrow + s * 64;
                float4 va = *(const float4*)(X + (size_t)(bm + row) * 512 + k0 + lkq);
                As[nb][lkq + 0][row] = va.x; As[nb][lkq + 1][row] = va.y;
                As[nb][lkq + 2][row] = va.z; As[nb][lkq + 3][row] = va.w;
                float4 vb = *(const float4*)(Wp + (size_t)(bn + row) * 512 + k0 + lkq);
                Bs[nb][lkq + 0][row] = vb.x; Bs[nb][lkq + 1][row] = vb.y;
                Bs[nb][lkq + 2][row] = vb.z; Bs[nb][lkq + 3][row] = vb.w;
            }
        }
        #pragma unroll
        for (int kk = 0; kk < 16; ++kk) {
            float4 a0 = *(const float4*)&As[buf][kk][m0];
            float4 a1 = *(const float4*)&As[buf][kk][m0 + 4];
            float4 b0 = *(const float4*)&Bs[buf][kk][n0];
            float4 b1 = *(const float4*)&Bs[buf][kk][n0 + 4];
            float a[8] = {a0.x, a0.y, a0.z, a0.w, a1.x, a1.y, a1.z, a1.w};
            float b[8] = {b0.x, b0.y, b0.z, b0.w, b1.x, b1.y, b1.z, b1.w};
            #pragma unroll
            for (int i2 = 0; i2 < 8; ++i2)
                #pragma unroll
                for (int j = 0; j < 8; ++j)
                    acc[i2][j] += a[i2] * b[j];
        }
        __syncthreads();
    }

    #pragma unroll
    for (int i2 = 0; i2 < 8; ++i2) {
        float* po = out + (size_t)(bm + m0 + i2) * 1024 + bn + n0;
        float4 o0v = make_float4(acc[i2][0], acc[i2][1], acc[i2][2], acc[i2][3]);
        float4 o1v = make_float4(acc[i2][4], acc[i2][5], acc[i2][6], acc[i2][7]);
        *(float4*)po = o0v;
        *(float4*)(po + 4) = o1v;
    }
}

// ---------------------------------------------------------------------------
extern "C" void kernel_launch(void* const* d_in, const int* in_sizes, int n_in,
                              void* d_out, int out_size) {
    const float* x  = (const float*)d_in[0];
    const float* U0 = (const float*)d_in[1];
    const float* Wa = (const float*)d_in[2];
    const float* La = (const float*)d_in[3];
    const float* Ra = (const float*)d_in[4];
    const float* Wb = (const float*)d_in[5];
    const float* Lb = (const float*)d_in[6];
    const float* Rb = (const float*)d_in[7];
    float* out = (float*)d_out;
    (void)in_sizes; (void)n_in; (void)out_size;

    reduce_partial_k<<<256, 512>>>(x);
    finalize_ab_k<<<1, 512>>>(Wa, Wb);
    compute_S_k<<<48, 256>>>(La, Ra, Rb);
    compute_F0_k<<<128, 256>>>(U0, La, Ra, Lb);
    rk4_k<<<128, 256>>>();
    expand_W_k<<<128, 256>>>(U0, La, Ra, Rb);
    gemm_k<<<dim3(8, 256), 256>>>(x, out);
}

// round 2
// speedup vs baseline: 1.8549x; 1.8549x over previous
#include <cuda_runtime.h>
#include <cuda_bf16.h>
#include <cstddef>
#include <cstdint>

// ---------------------------------------------------------------------------
// GeoDynamicLayer: out = x @ W^T, W = RK4(dU/dt = U A + G).
// Factored RK4 (24-dim row space) as in round 1, then tensor-core GEMM:
//   fp32 emulated via bf16 split: x=xhi+xlo, W=Whi+Wlo,
//   out = xhi Whi^T + xhi Wlo^T + xlo Whi^T   (error ~2^-18)
// ---------------------------------------------------------------------------

__device__ float g_partial[256 * 512];
__device__ float g_ab[16];
__device__ float g_S[24 * 16];
__device__ float g_F0[1024 * 24];
__device__ float g_P[1024 * 24];
__device__ __nv_bfloat16 g_xhi[32768 * 512];
__device__ __nv_bfloat16 g_xlo[32768 * 512];
__device__ __nv_bfloat16 g_Whi[1024 * 512];
__device__ __nv_bfloat16 g_Wlo[1024 * 512];

// ---------------- Stage 1: convert x -> bf16 hi/lo + column partial sums ----
__global__ void convert_reduce_k(const float* __restrict__ x) {
    int t = threadIdx.x;                 // 0..511 = column
    int rowStart = blockIdx.x * 128;
    const float* p = x + (size_t)rowStart * 512 + t;
    float s = 0.f;
    #pragma unroll 4
    for (int r = 0; r < 128; ++r) {
        float v = p[(size_t)r * 512];
        s += v;
        __nv_bfloat16 hi = __float2bfloat16_rn(v);
        __nv_bfloat16 lo = __float2bfloat16_rn(v - __bfloat162float(hi));
        size_t idx = (size_t)(rowStart + r) * 512 + t;
        g_xhi[idx] = hi;
        g_xlo[idx] = lo;
    }
    g_partial[blockIdx.x * 512 + t] = s;
}

// ---------------- Stage 2: xbar, abar = xbar@Wa, bbar = xbar@Wb -------------
__global__ void finalize_ab_k(const float* __restrict__ Wa,
                              const float* __restrict__ Wb) {
    __shared__ float sx[512];
    int t = threadIdx.x;
    float s = 0.f;
    #pragma unroll 8
    for (int p = 0; p < 256; ++p) s += g_partial[p * 512 + t];
    s *= (1.0f / 32768.0f);
    sx[t] = s;
    __syncthreads();
    int w = t >> 5, lane = t & 31;
    const float* Wm = (w < 8) ? Wa : Wb;
    int r = w & 7;
    float acc = 0.f;
    #pragma unroll
    for (int q = 0; q < 16; ++q) {
        int i = lane + q * 32;
        acc += sx[i] * Wm[i * 8 + r];
    }
    #pragma unroll
    for (int off = 16; off; off >>= 1)
        acc += __shfl_xor_sync(0xffffffffu, acc, off);
    if (lane == 0) g_ab[w] = acc;
}

// ---------------- Stage 3: S (24x16) ----------------------------------------
__global__ void compute_S_k(const float* __restrict__ La,
                            const float* __restrict__ Ra,
                            const float* __restrict__ Rb) {
    int gw = (blockIdx.x * blockDim.x + threadIdx.x) >> 5;
    int lane = threadIdx.x & 31;
    if (gw >= 384) return;
    int k = gw >> 4, c = gw & 15;
    const float* Vk = (k < 8) ? La : ((k < 16) ? Ra : Rb);
    int kk = k & 7;
    const float* M = (c < 8) ? Ra : La;
    int r = c & 7;
    float acc = 0.f;
    #pragma unroll
    for (int q = 0; q < 16; ++q) {
        int i = lane + q * 32;
        acc += Vk[i * 8 + kk] * M[i * 8 + r];
    }
    #pragma unroll
    for (int off = 16; off; off >>= 1)
        acc += __shfl_xor_sync(0xffffffffu, acc, off);
    if (lane == 0) {
        float d = g_ab[r];
        g_S[k * 16 + c] = (c < 8) ? (-acc * d) : (acc * d);
    }
}

// ---------------- Stage 4: F0 (1024x24) -------------------------------------
__global__ void compute_F0_k(const float* __restrict__ U0,
                             const float* __restrict__ La,
                             const float* __restrict__ Ra,
                             const float* __restrict__ Lb) {
    int w = (blockIdx.x * blockDim.x + threadIdx.x) >> 5;
    int lane = threadIdx.x & 31;
    const float* u = U0 + (size_t)w * 512;
    float accA[8] = {0, 0, 0, 0, 0, 0, 0, 0};
    float accR[8] = {0, 0, 0, 0, 0, 0, 0, 0};
    #pragma unroll
    for (int q = 0; q < 16; ++q) {
        int i = lane + q * 32;
        float uv = u[i];
        float4 la0 = *(const float4*)(La + i * 8);
        float4 la1 = *(const float4*)(La + i * 8 + 4);
        float4 ra0 = *(const float4*)(Ra + i * 8);
        float4 ra1 = *(const float4*)(Ra + i * 8 + 4);
        accA[0] += uv * la0.x; accA[1] += uv * la0.y;
        accA[2] += uv * la0.z; accA[3] += uv * la0.w;
        accA[4] += uv * la1.x; accA[5] += uv * la1.y;
        accA[6] += uv * la1.z; accA[7] += uv * la1.w;
        accR[0] += uv * ra0.x; accR[1] += uv * ra0.y;
        accR[2] += uv * ra0.z; accR[3] += uv * ra0.w;
        accR[4] += uv * ra1.x; accR[5] += uv * ra1.y;
        accR[6] += uv * ra1.z; accR[7] += uv * ra1.w;
    }
    #pragma unroll
    for (int off = 16; off; off >>= 1) {
        #pragma unroll
        for (int r = 0; r < 8; ++r) {
            accA[r] += __shfl_xor_sync(0xffffffffu, accA[r], off);
            accR[r] += __shfl_xor_sync(0xffffffffu, accR[r], off);
        }
    }
    if (lane == 0) {
        #pragma unroll
        for (int r = 0; r < 8; ++r) {
            float da = g_ab[r];
            g_F0[w * 24 + r]     = -da * accR[r];
            g_F0[w * 24 + 8 + r] =  da * accA[r];
            float gb = 0.f;
            if (w >= 512) gb = g_ab[8 + r] * Lb[(w - 512) * 8 + r];
            g_F0[w * 24 + 16 + r] = gb;
        }
    }
}

// ---------------- Stage 5: RK4 in 24-dim coefficient space ------------------
__global__ void rk4_k() {
    int row = (blockIdx.x * blockDim.x + threadIdx.x) >> 5;
    int lane = threadIdx.x & 31;
    float scol[24];
    #pragma unroll
    for (int k = 0; k < 24; ++k)
        scol[k] = (lane < 16) ? g_S[k * 16 + lane] : 0.f;
    float f0 = (lane < 24) ? g_F0[row * 24 + lane] : 0.f;
    float p[24];
    #pragma unroll
    for (int k = 0; k < 24; ++k) p[k] = 0.f;
    const float dt = 1.0f / 8.0f;
    for (int step = 0; step < 8; ++step) {
        float v[24], acc[24];
        #pragma unroll
        for (int k = 0; k < 24; ++k) v[k] = p[k];
        float kc = f0;
        #pragma unroll
        for (int k = 0; k < 24; ++k) kc += v[k] * scol[k];
        #pragma unroll
        for (int k = 0; k < 24; ++k) {
            float kf = __shfl_sync(0xffffffffu, kc, k);
            acc[k] = kf;
            v[k] = p[k] + 0.5f * dt * kf;
        }
        kc = f0;
        #pragma unroll
        for (int k = 0; k < 24; ++k) kc += v[k] * scol[k];
        #pragma unroll
        for (int k = 0; k < 24; ++k) {
            float kf = __shfl_sync(0xffffffffu, kc, k);
            acc[k] += 2.0f * kf;
            v[k] = p[k] + 0.5f * dt * kf;
        }
        kc = f0;
        #pragma unroll
        for (int k = 0; k < 24; ++k) kc += v[k] * scol[k];
        #pragma unroll
        for (int k = 0; k < 24; ++k) {
            float kf = __shfl_sync(0xffffffffu, kc, k);
            acc[k] += 2.0f * kf;
            v[k] = p[k] + dt * kf;
        }
        kc = f0;
        #pragma unroll
        for (int k = 0; k < 24; ++k) kc += v[k] * scol[k];
        #pragma unroll
        for (int k = 0; k < 24; ++k) {
            float kf = __shfl_sync(0xffffffffu, kc, k);
            acc[k] += kf;
        }
        #pragma unroll
        for (int k = 0; k < 24; ++k) p[k] += (dt / 6.0f) * acc[k];
    }
    if (lane < 24) g_P[row * 24 + lane] = p[lane];
}

// ---------------- Stage 6: W = U0 + P V2^T  -> bf16 hi/lo -------------------
__global__ void expand_W_k(const float* __restrict__ U0,
                           const float* __restrict__ La,
                           const float* __restrict__ Ra,
                           const float* __restrict__ Rb) {
    __shared__ float sP[8 * 24];
    int t = threadIdx.x;
    int o0 = blockIdx.x * 8;
    if (t < 192) sP[t] = g_P[o0 * 24 + t];
    __syncthreads();
    #pragma unroll
    for (int half = 0; half < 2; ++half) {
        int i = t + half * 256;
        float v2[24];
        float4 q;
        q = *(const float4*)(La + i * 8);
        v2[0] = q.x; v2[1] = q.y; v2[2] = q.z; v2[3] = q.w;
        q = *(const float4*)(La + i * 8 + 4);
        v2[4] = q.x; v2[5] = q.y; v2[6] = q.z; v2[7] = q.w;
        q = *(const float4*)(Ra + i * 8);
        v2[8] = q.x; v2[9] = q.y; v2[10] = q.z; v2[11] = q.w;
        q = *(const float4*)(Ra + i * 8 + 4);
        v2[12] = q.x; v2[13] = q.y; v2[14] = q.z; v2[15] = q.w;
        q = *(const float4*)(Rb + i * 8);
        v2[16] = q.x; v2[17] = q.y; v2[18] = q.z; v2[19] = q.w;
        q = *(const float4*)(Rb + i * 8 + 4);
        v2[20] = q.x; v2[21] = q.y; v2[22] = q.z; v2[23] = q.w;
        #pragma unroll
        for (int r = 0; r < 8; ++r) {
            float accv = U0[(size_t)(o0 + r) * 512 + i];
            #pragma unroll
            for (int k = 0; k < 24; ++k) accv += sP[r * 24 + k] * v2[k];
            __nv_bfloat16 hi = __float2bfloat16_rn(accv);
            __nv_bfloat16 lo = __float2bfloat16_rn(accv - __bfloat162float(hi));
            size_t idx = (size_t)(o0 + r) * 512 + i;
            g_Whi[idx] = hi;
            g_Wlo[idx] = lo;
        }
    }
}

// ---------------- Stage 7: tensor-core GEMM  out = x @ W^T ------------------
// 3 bf16 passes over K (xhi*Whi + xhi*Wlo + xlo*Whi), fused as 48 K-chunks.
// CTA tile 128x128, BK=32, 8 warps (4x2), warp tile 32x64, mma.m16n8k16.
// smem rows padded to 5x16B (80B) -> conflict-free ldmatrix, double-buffered
// cp.async pipeline.

#define CP16(sa, ga) \
    asm volatile("cp.async.cg.shared.global [%0], [%1], 16;\n" :: "r"(sa), "l"(ga))

__device__ __forceinline__ void ldm_x4(uint32_t& r0, uint32_t& r1,
                                       uint32_t& r2, uint32_t& r3, uint32_t a) {
    asm volatile("ldmatrix.sync.aligned.m8n8.x4.shared.b16 {%0,%1,%2,%3}, [%4];"
                 : "=r"(r0), "=r"(r1), "=r"(r2), "=r"(r3) : "r"(a));
}

__device__ __forceinline__ void mma16816(float* c, const uint32_t* a,
                                         const uint32_t* b) {
    asm volatile(
        "mma.sync.aligned.m16n8k16.row.col.f32.bf16.bf16.f32 "
        "{%0,%1,%2,%3}, {%4,%5,%6,%7}, {%8,%9}, {%0,%1,%2,%3};"
        : "+f"(c[0]), "+f"(c[1]), "+f"(c[2]), "+f"(c[3])
        : "r"(a[0]), "r"(a[1]), "r"(a[2]), "r"(a[3]), "r"(b[0]), "r"(b[1]));
}

__global__ __launch_bounds__(256) void gemm_tc_k(float* __restrict__ out) {
    // per buffer: 128 rows * 5 units * 16B = 10 KB
    __shared__ __align__(16) __nv_bfloat16 smA[2][128 * 5 * 8];
    __shared__ __align__(16) __nv_bfloat16 smB[2][128 * 5 * 8];

    int tid = threadIdx.x;
    int lane = tid & 31;
    int w = tid >> 5;
    int wm = (w & 3) * 32;       // warp m offset in tile
    int wn = (w >> 2) * 64;      // warp n offset in tile
    int bm = blockIdx.y * 128;
    int bn = blockIdx.x * 128;

    uint32_t saA[2], saB[2];
    saA[0] = (uint32_t)__cvta_generic_to_shared(&smA[0][0]);
    saA[1] = (uint32_t)__cvta_generic_to_shared(&smA[1][0]);
    saB[0] = (uint32_t)__cvta_generic_to_shared(&smB[0][0]);
    saB[1] = (uint32_t)__cvta_generic_to_shared(&smB[1][0]);

    float c[2][8][4];
    #pragma unroll
    for (int mi = 0; mi < 2; ++mi)
        #pragma unroll
        for (int ni = 0; ni < 8; ++ni)
            #pragma unroll
            for (int q = 0; q < 4; ++q) c[mi][ni][q] = 0.f;

    // load thread mapping: lin over 128 rows x 4 units
    int lr0 = tid >> 2;          // rows tid/4 and tid/4+64
    int lu = tid & 3;

    auto issue_chunk = [&](int i, int buf) {
        int pass = i >> 4;
        int ko = (i & 15) << 5;
        const __nv_bfloat16* Ab = (pass < 2) ? g_xhi : g_xlo;
        const __nv_bfloat16* Bb = (pass == 1) ? g_Wlo : g_Whi;
        #pragma unroll
        for (int j = 0; j < 2; ++j) {
            int r = lr0 + j * 64;
            const __nv_bfloat16* ga = Ab + (size_t)(bm + r) * 512 + ko + lu * 8;
            CP16(saA[buf] + ((r * 5 + lu) << 4), ga);
            const __nv_bfloat16* gb = Bb + (size_t)(bn + r) * 512 + ko + lu * 8;
            CP16(saB[buf] + ((r * 5 + lu) << 4), gb);
        }
        asm volatile("cp.async.commit_group;\n" ::);
    };

    issue_chunk(0, 0);

    int mg = lane >> 3, rr = lane & 7;

    for (int i = 0; i < 48; ++i) {
        int buf = i & 1;
        if (i + 1 < 48) {
            issue_chunk(i + 1, buf ^ 1);
            asm volatile("cp.async.wait_group 1;\n" ::);
        } else {
            asm volatile("cp.async.wait_group 0;\n" ::);
        }
        __syncthreads();

        #pragma unroll
        for (int ks = 0; ks < 2; ++ks) {
            uint32_t a[2][4];
            #pragma unroll
            for (int mi = 0; mi < 2; ++mi) {
                int row = wm + mi * 16 + (mg & 1) * 8 + rr;
                int ku = ks * 2 + (mg >> 1);
                ldm_x4(a[mi][0], a[mi][1], a[mi][2], a[mi][3],
                       saA[buf] + ((row * 5 + ku) << 4));
            }
            uint32_t b[8][2];
            #pragma unroll
            for (int j = 0; j < 4; ++j) {
                int row = wn + j * 16 + (mg >> 1) * 8 + rr;
                int ku = ks * 2 + (mg & 1);
                ldm_x4(b[2 * j][0], b[2 * j][1], b[2 * j + 1][0], b[2 * j + 1][1],
                       saB[buf] + ((row * 5 + ku) << 4));
            }
            #pragma unroll
            for (int mi = 0; mi < 2; ++mi)
                #pragma unroll
                for (int ni = 0; ni < 8; ++ni)
                    mma16816(c[mi][ni], a[mi], b[ni]);
        }
        __syncthreads();
    }

    // epilogue
    int gid = lane >> 2, tig = lane & 3;
    #pragma unroll
    for (int mi = 0; mi < 2; ++mi) {
        #pragma unroll
        for (int ni = 0; ni < 8; ++ni) {
            int row0 = bm + wm + mi * 16 + gid;
            int col = bn + wn + ni * 8 + tig * 2;
            float2* p0 = (float2*)(out + (size_t)row0 * 1024 + col);
            *p0 = make_float2(c[mi][ni][0], c[mi][ni][1]);
            float2* p1 = (float2*)(out + (size_t)(row0 + 8) * 1024 + col);
            *p1 = make_float2(c[mi][ni][2], c[mi][ni][3]);
        }
    }
}

// ---------------------------------------------------------------------------
extern "C" void kernel_launch(void* const* d_in, const int* in_sizes, int n_in,
                              void* d_out, int out_size) {
    const float* x  = (const float*)d_in[0];
    const float* U0 = (const float*)d_in[1];
    const float* Wa = (const float*)d_in[2];
    const float* La = (const float*)d_in[3];
    const float* Ra = (const float*)d_in[4];
    const float* Wb = (const float*)d_in[5];
    const float* Lb = (const float*)d_in[6];
    const float* Rb = (const float*)d_in[7];
    float* out = (float*)d_out;
    (void)in_sizes; (void)n_in; (void)out_size;

    convert_reduce_k<<<256, 512>>>(x);
    finalize_ab_k<<<1, 512>>>(Wa, Wb);
    compute_S_k<<<48, 256>>>(La, Ra, Rb);
    compute_F0_k<<<128, 256>>>(U0, La, Ra, Lb);
    rk4_k<<<128, 256>>>();
    expand_W_k<<<128, 256>>>(U0, La, Ra, Rb);
    gemm_tc_k<<<dim3(8, 256), 256>>>(out);
}